// round 7
// baseline (speedup 1.0000x reference)
#include <cuda_runtime.h>

// AnnularDilatedKNN: B=4, N=4096, C=64, SAMPLE=16, DILATED_RATE=2 -> NSAMPLE=32, K_out=16
// radius^2 = 256.
//
// R7: grid retained, execution shape fixed.
//  - build: 4 full-chip micro-kernels (zero/count/scan/scatter) -> cell-sorted
//    AoS float4(x,y,z,sq) + original ids + CSR starts.
//  - query: thread-per-query in SORTED order (warp = adjacent queries), 2 threads
//    per query split the 9 runs; hits -> pair-private smem bitmap (atomicOr);
//    per-thread popc/ffs selection of positions {0,16..30}, pad with center.
//  - gathers unchanged. Predicate arithmetic byte-identical to rel_err=0 kernels.

#define NB    4
#define NP    4096
#define KOUT  16
#define NC    20
#define NCELL (NC * NC * NC)
#define CMIN  (-170.0f)
#define INVCELL (1.0f / 17.0f)

__device__ float4 g_cand[NB * NP];          // cell-sorted (x,y,z,sq)
__device__ int    g_sid[NB * NP];           // original index per sorted slot
__device__ int    g_pcell[NB * NP];         // cell id per original point
__device__ int    g_ccnt[NB * NCELL];
__device__ int    g_cstart[NB * (NCELL + 1)];
__device__ int    g_cursor[NB * NCELL];
__device__ int    g_ids[NB * NP * KOUT];

__device__ __forceinline__ float sq3(float x, float y, float z) {
    // jnp.sum(xyz*xyz, -1): left-to-right, separately rounded products (no fma).
    return __fadd_rn(__fadd_rn(__fmul_rn(x, x), __fmul_rn(y, y)), __fmul_rn(z, z));
}

__device__ __forceinline__ int cell1(float v) {
    int c = (int)floorf(__fmul_rn(__fadd_rn(v, -CMIN), INVCELL));
    return min(max(c, 0), NC - 1);
}

// ---------------- build chain ----------------
__global__ __launch_bounds__(256) void zero_kernel() {
    const int i = blockIdx.x * 256 + threadIdx.x;
    if (i < NB * NCELL) g_ccnt[i] = 0;
}

__global__ __launch_bounds__(256) void count_kernel(const float* __restrict__ xyz) {
    const int i = blockIdx.x * 256 + threadIdx.x;      // 0..16383
    const int b = i >> 12;
    const float x = xyz[3 * i + 0];
    const float y = xyz[3 * i + 1];
    const float z = xyz[3 * i + 2];
    const int c = (cell1(z) * NC + cell1(y)) * NC + cell1(x);
    g_pcell[i] = c;
    atomicAdd(&g_ccnt[b * NCELL + c], 1);
}

__global__ __launch_bounds__(1024) void scan_kernel() {
    __shared__ int cnts[NCELL];
    __shared__ int wsum[32];
    const int b = blockIdx.x, tid = threadIdx.x;
    const int lane = tid & 31, wid = tid >> 5;

    for (int c = tid; c < NCELL; c += 1024) cnts[c] = g_ccnt[b * NCELL + c];
    __syncthreads();

    int v[8];
    int s = 0;
    #pragma unroll
    for (int j = 0; j < 8; ++j) {
        const int c = tid * 8 + j;
        const int t = (c < NCELL) ? cnts[c] : 0;
        v[j] = t; s += t;
    }
    int incl = s;
    #pragma unroll
    for (int off = 1; off < 32; off <<= 1) {
        const int t = __shfl_up_sync(0xffffffffu, incl, off);
        if (lane >= off) incl += t;
    }
    if (lane == 31) wsum[wid] = incl;
    __syncthreads();
    if (wid == 0) {
        const int w = wsum[lane];
        int wi = w;
        #pragma unroll
        for (int off = 1; off < 32; off <<= 1) {
            const int t = __shfl_up_sync(0xffffffffu, wi, off);
            if (lane >= off) wi += t;
        }
        wsum[lane] = wi - w;
    }
    __syncthreads();
    int run = (incl - s) + wsum[wid];
    #pragma unroll
    for (int j = 0; j < 8; ++j) {
        const int c = tid * 8 + j;
        if (c < NCELL) {
            g_cstart[b * (NCELL + 1) + c] = run;
            g_cursor[b * NCELL + c] = run;
        }
        run += v[j];
    }
    if (tid == 0) g_cstart[b * (NCELL + 1) + NCELL] = NP;
}

__global__ __launch_bounds__(256) void scatter_kernel(const float* __restrict__ xyz) {
    const int i = blockIdx.x * 256 + threadIdx.x;      // 0..16383
    const int b = i >> 12;
    const float x = xyz[3 * i + 0];
    const float y = xyz[3 * i + 1];
    const float z = xyz[3 * i + 2];
    const int c = g_pcell[i];
    const int pos = atomicAdd(&g_cursor[b * NCELL + c], 1);
    const int gi = (b << 12) + pos;
    g_cand[gi] = make_float4(x, y, z, sq3(x, y, z));
    g_sid[gi] = i & (NP - 1);
}

// ---------------- query: thread-pair per sorted query ----------------
#define QPB 64      // query pairs per block (128 threads)
__global__ __launch_bounds__(2 * QPB) void query_kernel() {
    __shared__ unsigned bm[128 * QPB];   // [word*QPB + pairLocal], 32KB

    const int tid = threadIdx.x;
    const int half = tid & 1;
    const int pl = tid >> 1;                       // pair-local 0..63
    const int p = blockIdx.x * QPB + pl;           // sorted global position
    const int b = p >> 12;
    const int base = b << 12;

    const float4 qc = g_cand[p];
    const int qn = g_sid[p];
    const float xn = qc.x, yn = qc.y, zn = qc.z, sqn = qc.w;

    for (int w = half; w < 128; w += 2) bm[w * QPB + pl] = 0u;
    __syncwarp();

    const int cx = cell1(xn), cy = cell1(yn), cz = cell1(zn);
    const int x0 = max(cx - 1, 0), x1 = min(cx + 1, NC - 1);
    const int y0 = max(cy - 1, 0), y1 = min(cy + 1, NC - 1);
    const int z0 = max(cz - 1, 0), z1 = min(cz + 1, NC - 1);
    const int* cs = g_cstart + b * (NCELL + 1);

    int run = 0;
    for (int zi = z0; zi <= z1; ++zi) {
        for (int yi = y0; yi <= y1; ++yi) {
            if ((run++ & 1) != half) continue;     // split runs between the pair
            const int row = (zi * NC + yi) * NC;
            const int s = cs[row + x0];
            const int e = cs[row + x1 + 1];
            for (int i = s; i < e; ++i) {
                const float4 c = g_cand[base + i];
                // byte-identical verified predicate
                const float dot = fmaf(zn, c.z, fmaf(yn, c.y, __fmul_rn(xn, c.x)));
                const float d2  = __fsub_rn(__fadd_rn(sqn, c.w), __fmul_rn(2.0f, dot));
                if (d2 < 256.0f) {
                    const int id = g_sid[base + i];
                    atomicOr(&bm[(id >> 5) * QPB + pl], 1u << (id & 31));
                }
            }
        }
    }
    __syncwarp();

    if (half == 0) {
        int cnt = 0, h0 = 0;
        int* o = g_ids + (((base + qn)) << 4);
        for (int w = 0; w < 128 && cnt < 31; ++w) {
            unsigned wv = bm[w * QPB + pl];
            while (wv) {
                const int id = (w << 5) + (__ffs(wv) - 1);
                if (cnt == 0)      { h0 = id; o[0] = id; }
                else if (cnt >= 16) o[cnt - 15] = id;
                ++cnt;
                if (cnt >= 31) break;
                wv &= wv - 1u;
            }
        }
        #pragma unroll
        for (int k = 1; k < 16; ++k)
            if (k + 15 >= cnt) o[k] = h0;          // pad with center
    }
}

// ---------------- gathers (unchanged) ----------------
__global__ __launch_bounds__(256) void gather_xyz_kernel(const float* __restrict__ xyz,
                                                         float* __restrict__ out) {
    const int t  = blockIdx.x * 256 + threadIdx.x;    // b(2)|n(12)|k4(2)
    const int k4 = t & 3;
    const int n  = (t >> 2) & (NP - 1);
    const int b  = t >> 14;
    const int bb = b << 12;
    const int4 id4 = reinterpret_cast<const int4*>(g_ids)[t];
    const int o4 = (n << 2) + k4;

    const float* xb = xyz + 3 * bb;
    const float x0 = xb[3 * id4.x], y0 = xb[3 * id4.x + 1], z0 = xb[3 * id4.x + 2];
    const float x1 = xb[3 * id4.y], y1 = xb[3 * id4.y + 1], z1 = xb[3 * id4.y + 2];
    const float x2 = xb[3 * id4.z], y2 = xb[3 * id4.z + 1], z2 = xb[3 * id4.z + 2];
    const float x3 = xb[3 * id4.w], y3 = xb[3 * id4.w + 1], z3 = xb[3 * id4.w + 2];
    float4* o = reinterpret_cast<float4*>(out);
    o[((b * 3 + 0) << 14) + o4] = make_float4(x0, x1, x2, x3);
    o[((b * 3 + 1) << 14) + o4] = make_float4(y0, y1, y2, y3);
    o[((b * 3 + 2) << 14) + o4] = make_float4(z0, z1, z2, z3);
}

__global__ __launch_bounds__(256) void gather_feat_kernel(const float* __restrict__ feat,
                                                          float* __restrict__ out) {
    const int t  = blockIdx.x * 256 + threadIdx.x;    // b(2)|n(12)|k4(2)|cq(2)
    const int cq = t & 3;
    const int k4 = (t >> 2) & 3;
    const int n  = (t >> 4) & (NP - 1);
    const int b  = t >> 16;
    const int bb = b << 12;
    const int4 id4 = reinterpret_cast<const int4*>(g_ids)[((bb + n) << 2) + k4];
    const int o4 = (n << 2) + k4;

    const float4* f0 = reinterpret_cast<const float4*>(feat) + ((bb + id4.x) << 4) + (cq << 2);
    const float4* f1 = reinterpret_cast<const float4*>(feat) + ((bb + id4.y) << 4) + (cq << 2);
    const float4* f2 = reinterpret_cast<const float4*>(feat) + ((bb + id4.z) << 4) + (cq << 2);
    const float4* f3 = reinterpret_cast<const float4*>(feat) + ((bb + id4.w) << 4) + (cq << 2);

    float4* of = reinterpret_cast<float4*>(out) + ((12 + b * 64 + (cq << 4)) << 14) + o4;
    #pragma unroll
    for (int j = 0; j < 4; ++j) {
        const float4 v0 = f0[j], v1 = f1[j], v2 = f2[j], v3 = f3[j];
        of[(4 * j + 0) << 14] = make_float4(v0.x, v1.x, v2.x, v3.x);
        of[(4 * j + 1) << 14] = make_float4(v0.y, v1.y, v2.y, v3.y);
        of[(4 * j + 2) << 14] = make_float4(v0.z, v1.z, v2.z, v3.z);
        of[(4 * j + 3) << 14] = make_float4(v0.w, v1.w, v2.w, v3.w);
    }
}

extern "C" void kernel_launch(void* const* d_in, const int* in_sizes, int n_in,
                              void* d_out, int out_size) {
    const float* xyz  = (const float*)d_in[0];
    const float* feat = (const float*)d_in[1];
    float* out = (float*)d_out;

    zero_kernel<<<(NB * NCELL + 255) / 256, 256>>>();
    count_kernel<<<(NB * NP) / 256, 256>>>(xyz);
    scan_kernel<<<NB, 1024>>>();
    scatter_kernel<<<(NB * NP) / 256, 256>>>(xyz);
    query_kernel<<<(NB * NP) / QPB, 2 * QPB>>>();
    gather_xyz_kernel<<<(NB * NP * 4) / 256, 256>>>(xyz, out);
    gather_feat_kernel<<<(NB * NP * KOUT) / 256, 256>>>(feat, out);
}

// round 8
// speedup vs baseline: 1.5492x; 1.5492x over previous
#include <cuda_runtime.h>

// AnnularDilatedKNN: B=4, N=4096, C=64, SAMPLE=16, DILATED_RATE=2 -> NSAMPLE=32, K_out=16
// radius^2 = 256.
//
// R8: R5's winning shape (warp-per-query, smem-staged, coalesced LDS.128) +
// 1-D z-slab pruning (20 slabs, width 17): candidates become ONE contiguous
// span of the z-sorted array (~45% of N), scanned with no early-exit break
// (pipelinable). Hits recorded order-independently in a per-warp bitmap over
// ORIGINAL ids; selection = R6-verified popc-prefix + binary search.
// Build = 3 micro-kernels with no global atomics.
// Predicate arithmetic byte-identical to all rel_err=0.0 kernels.

#define NB    4
#define NP    4096
#define KOUT  16
#define NSLAB 20
#define CMIN  (-170.0f)
#define INVSLAB (1.0f / 17.0f)
#define QW    16            // queries (warps) per query block
#define CBLK  64            // count/scatter blocks (256 threads each)

__device__ float4 g_cand[NB * NP];          // z-slab-sorted (x,y,z,sq)
__device__ int    g_sid[NB * NP];           // original index per sorted slot
__device__ int    g_pslab[NB * NP];         // slab per original point
__device__ int    g_blkcnt[CBLK * NSLAB];   // per count-block slab counts
__device__ int    g_blkbase[CBLK * NSLAB];  // per count-block slab bases
__device__ int    g_sstart[NB * (NSLAB + 1)];
__device__ int    g_ids[NB * NP * KOUT];

__device__ __forceinline__ float sq3(float x, float y, float z) {
    // jnp.sum(xyz*xyz, -1): left-to-right, separately rounded products (no fma).
    return __fadd_rn(__fadd_rn(__fmul_rn(x, x), __fmul_rn(y, y)), __fmul_rn(z, z));
}

__device__ __forceinline__ int slab1(float v) {
    int c = (int)floorf(__fmul_rn(__fadd_rn(v, -CMIN), INVSLAB));
    return min(max(c, 0), NSLAB - 1);
}

// ---- build 1: per-block slab counts (no global atomics; plain overwrite) ----
__global__ __launch_bounds__(256) void count_kernel(const float* __restrict__ xyz) {
    __shared__ int sc[NSLAB];
    const int i = blockIdx.x * 256 + threadIdx.x;      // block spans one batch
    if (threadIdx.x < NSLAB) sc[threadIdx.x] = 0;
    __syncthreads();
    const int s = slab1(xyz[3 * i + 2]);
    g_pslab[i] = s;
    atomicAdd(&sc[s], 1);
    __syncthreads();
    if (threadIdx.x < NSLAB)
        g_blkcnt[blockIdx.x * NSLAB + threadIdx.x] = sc[threadIdx.x];
}

// ---- build 2: slab starts + per-block bases (1 block, warp per batch) ----
__global__ __launch_bounds__(128) void scan_kernel() {
    const int b = threadIdx.x >> 5;                    // batch
    const int lane = threadIdx.x & 31;
    int cnts[16];
    int tot = 0;
    if (lane < NSLAB) {
        #pragma unroll
        for (int k = 0; k < 16; ++k) {
            cnts[k] = g_blkcnt[(b * 16 + k) * NSLAB + lane];
            tot += cnts[k];
        }
    }
    int incl = (lane < NSLAB) ? tot : 0;
    #pragma unroll
    for (int off = 1; off < 32; off <<= 1) {
        const int t = __shfl_up_sync(0xffffffffu, incl, off);
        if (lane >= off) incl += t;
    }
    if (lane < NSLAB) {
        const int excl = incl - tot;
        g_sstart[b * (NSLAB + 1) + lane] = excl;
        if (lane == NSLAB - 1) g_sstart[b * (NSLAB + 1) + NSLAB] = incl;  // == NP
        int run = excl;
        #pragma unroll
        for (int k = 0; k < 16; ++k) {
            g_blkbase[(b * 16 + k) * NSLAB + lane] = run;
            run += cnts[k];
        }
    }
}

// ---- build 3: scatter into sorted order (smem atomics only) ----
__global__ __launch_bounds__(256) void scatter_kernel(const float* __restrict__ xyz) {
    __shared__ int sc[NSLAB];
    __shared__ int sb[NSLAB];
    const int i = blockIdx.x * 256 + threadIdx.x;
    const int b = i >> 12;
    if (threadIdx.x < NSLAB) {
        sc[threadIdx.x] = 0;
        sb[threadIdx.x] = g_blkbase[blockIdx.x * NSLAB + threadIdx.x];
    }
    __syncthreads();
    const int s = g_pslab[i];
    const int lr = atomicAdd(&sc[s], 1);
    const float x = xyz[3 * i + 0];
    const float y = xyz[3 * i + 1];
    const float z = xyz[3 * i + 2];
    const int gi = (b << 12) + sb[s] + lr;
    g_cand[gi] = make_float4(x, y, z, sq3(x, y, z));
    g_sid[gi] = i & (NP - 1);
}

// ---- query: warp per query over the contiguous z-span, bitmap hits ----
__global__ __launch_bounds__(32 * QW) void query_kernel(const float* __restrict__ xyz) {
    extern __shared__ float4 s_cand[];                 // NP float4 = 64KB
    __shared__ unsigned bm[QW][128];
    __shared__ int cum[QW][128];

    const int warp = threadIdx.x >> 5, lane = threadIdx.x & 31;
    const int q = blockIdx.x * QW + warp;
    const int b = q >> 12, n = q & (NP - 1);
    const int bb = b << 12;

    {   // stage the batch's sorted candidates (coalesced float4)
        const float4* gc = g_cand + bb;
        for (int i = threadIdx.x; i < NP; i += 32 * QW) s_cand[i] = gc[i];
    }
    #pragma unroll
    for (int j = 0; j < 4; ++j) bm[warp][lane * 4 + j] = 0u;
    __syncthreads();

    const float xn = xyz[3 * (bb + n) + 0];
    const float yn = xyz[3 * (bb + n) + 1];
    const float zn = xyz[3 * (bb + n) + 2];
    const float sqn = sq3(xn, yn, zn);

    const int sz = slab1(zn);
    const int s = g_sstart[b * (NSLAB + 1) + max(sz - 1, 0)];
    const int e = g_sstart[b * (NSLAB + 1) + min(sz + 1, NSLAB - 1) + 1];
    const int* __restrict__ sid = g_sid + bb;

    #pragma unroll 4
    for (int i = s + lane; i < e; i += 32) {
        const float4 c = s_cand[i];
        // byte-identical verified predicate
        const float dot = fmaf(zn, c.z, fmaf(yn, c.y, __fmul_rn(xn, c.x)));
        const float d2  = __fsub_rn(__fadd_rn(sqn, c.w), __fmul_rn(2.0f, dot));
        if (d2 < 256.0f) {
            const int id = sid[i];
            atomicOr(&bm[warp][id >> 5], 1u << (id & 31));
        }
    }
    __syncwarp();

    // selection (R6-verified): popc prefix over 128 words, pick ranks {0,16..30}
    int c4[4];
    int lsum = 0;
    #pragma unroll
    for (int j = 0; j < 4; ++j) {
        c4[j] = __popc(bm[warp][lane * 4 + j]);
        lsum += c4[j];
    }
    int incl = lsum;
    #pragma unroll
    for (int off = 1; off < 32; off <<= 1) {
        const int t = __shfl_up_sync(0xffffffffu, incl, off);
        if (lane >= off) incl += t;
    }
    const int cnt = __shfl_sync(0xffffffffu, incl, 31);
    int base = incl - lsum;
    #pragma unroll
    for (int j = 0; j < 4; ++j) {
        cum[warp][lane * 4 + j] = base;
        base += c4[j];
    }
    __syncwarp();

    int own = 0;
    const int t = (lane == 0) ? 0 : lane + 15;
    if (lane < 16 && t < cnt) {
        int lo = 0, hi = 127;
        while (lo < hi) {                              // largest word with cum <= t
            const int mid = (lo + hi + 1) >> 1;
            if (cum[warp][mid] <= t) lo = mid; else hi = mid - 1;
        }
        unsigned w = bm[warp][lo];
        int r = t - cum[warp][lo];
        while (r--) w &= (w - 1u);
        own = (lo << 5) + (__ffs(w) - 1);
    }
    const int h0 = __shfl_sync(0xffffffffu, own, 0);   // center (cnt >= 1: self-hit)
    if (lane < 16) g_ids[(q << 4) + lane] = (t < cnt) ? own : h0;
}

// ---------------- gathers (unchanged, verified) ----------------
__global__ __launch_bounds__(256) void gather_xyz_kernel(const float* __restrict__ xyz,
                                                         float* __restrict__ out) {
    const int t  = blockIdx.x * 256 + threadIdx.x;    // b(2)|n(12)|k4(2)
    const int k4 = t & 3;
    const int n  = (t >> 2) & (NP - 1);
    const int b  = t >> 14;
    const int bb = b << 12;
    const int4 id4 = reinterpret_cast<const int4*>(g_ids)[t];
    const int o4 = (n << 2) + k4;

    const float* xb = xyz + 3 * bb;
    const float x0 = xb[3 * id4.x], y0 = xb[3 * id4.x + 1], z0 = xb[3 * id4.x + 2];
    const float x1 = xb[3 * id4.y], y1 = xb[3 * id4.y + 1], z1 = xb[3 * id4.y + 2];
    const float x2 = xb[3 * id4.z], y2 = xb[3 * id4.z + 1], z2 = xb[3 * id4.z + 2];
    const float x3 = xb[3 * id4.w], y3 = xb[3 * id4.w + 1], z3 = xb[3 * id4.w + 2];
    float4* o = reinterpret_cast<float4*>(out);
    o[((b * 3 + 0) << 14) + o4] = make_float4(x0, x1, x2, x3);
    o[((b * 3 + 1) << 14) + o4] = make_float4(y0, y1, y2, y3);
    o[((b * 3 + 2) << 14) + o4] = make_float4(z0, z1, z2, z3);
}

__global__ __launch_bounds__(256) void gather_feat_kernel(const float* __restrict__ feat,
                                                          float* __restrict__ out) {
    const int t  = blockIdx.x * 256 + threadIdx.x;    // b(2)|n(12)|k4(2)|cq(2)
    const int cq = t & 3;
    const int k4 = (t >> 2) & 3;
    const int n  = (t >> 4) & (NP - 1);
    const int b  = t >> 16;
    const int bb = b << 12;
    const int4 id4 = reinterpret_cast<const int4*>(g_ids)[((bb + n) << 2) + k4];
    const int o4 = (n << 2) + k4;

    const float4* f0 = reinterpret_cast<const float4*>(feat) + ((bb + id4.x) << 4) + (cq << 2);
    const float4* f1 = reinterpret_cast<const float4*>(feat) + ((bb + id4.y) << 4) + (cq << 2);
    const float4* f2 = reinterpret_cast<const float4*>(feat) + ((bb + id4.z) << 4) + (cq << 2);
    const float4* f3 = reinterpret_cast<const float4*>(feat) + ((bb + id4.w) << 4) + (cq << 2);

    float4* of = reinterpret_cast<float4*>(out) + ((12 + b * 64 + (cq << 4)) << 14) + o4;
    #pragma unroll
    for (int j = 0; j < 4; ++j) {
        const float4 v0 = f0[j], v1 = f1[j], v2 = f2[j], v3 = f3[j];
        of[(4 * j + 0) << 14] = make_float4(v0.x, v1.x, v2.x, v3.x);
        of[(4 * j + 1) << 14] = make_float4(v0.y, v1.y, v2.y, v3.y);
        of[(4 * j + 2) << 14] = make_float4(v0.z, v1.z, v2.z, v3.z);
        of[(4 * j + 3) << 14] = make_float4(v0.w, v1.w, v2.w, v3.w);
    }
}

extern "C" void kernel_launch(void* const* d_in, const int* in_sizes, int n_in,
                              void* d_out, int out_size) {
    const float* xyz  = (const float*)d_in[0];
    const float* feat = (const float*)d_in[1];
    float* out = (float*)d_out;

    cudaFuncSetAttribute(query_kernel,
                         cudaFuncAttributeMaxDynamicSharedMemorySize, NP * 16);
    cudaFuncSetAttribute(query_kernel,
                         cudaFuncAttributePreferredSharedMemoryCarveout, 100);

    count_kernel<<<CBLK, 256>>>(xyz);
    scan_kernel<<<1, 128>>>();
    scatter_kernel<<<CBLK, 256>>>(xyz);
    query_kernel<<<(NB * NP) / QW, 32 * QW, NP * 16>>>(xyz);
    gather_xyz_kernel<<<(NB * NP * 4) / 256, 256>>>(xyz, out);
    gather_feat_kernel<<<(NB * NP * KOUT) / 256, 256>>>(feat, out);
}